// round 3
// baseline (speedup 1.0000x reference)
#include <cuda_runtime.h>
#include <cuda_fp16.h>

// Problem constants
#define D_IN   4096
#define D_HID  2048
#define D_OUT  512
#define NBATCH 8192
#define NNZ1   32768
#define NNZ2   8192
#define TB     16     // batch rows per block
#define STRIDE 64     // padded edges per output row (max Poisson(16) << 64)

// ---------------- scratch (__device__ globals; no allocation allowed) --------
__device__ float4 g_edge1[D_HID * STRIDE / 2];   // {w,col} pairs, 2 edges/float4
__device__ float4 g_edge2[D_OUT * STRIDE / 2];
__device__ int    g_cnt1[D_HID];
__device__ int    g_cnt2[D_OUT];
__device__ int    g_desc1[D_HID];                // count-sorted (row<<8)|cnt
__device__ int    g_desc2[D_OUT];

// ---------------- prep kernels ------------------------------------------------
__global__ void k_zero() {
    int i = blockIdx.x * blockDim.x + threadIdx.x;
    if (i < D_HID) g_cnt1[i] = 0;
    if (i < D_OUT) g_cnt2[i] = 0;
}

__global__ void k_scatter(const float* __restrict__ w1, const int* __restrict__ rows1,
                          const int* __restrict__ cols1,
                          const float* __restrict__ w2, const int* __restrict__ rows2,
                          const int* __restrict__ cols2) {
    int e = blockIdx.x * blockDim.x + threadIdx.x;
    float2* e1 = reinterpret_cast<float2*>(g_edge1);
    float2* e2 = reinterpret_cast<float2*>(g_edge2);
    if (e < NNZ1) {
        int r = rows1[e];
        int p = atomicAdd(&g_cnt1[r], 1);
        if (p < STRIDE) e1[r * STRIDE + p] = make_float2(w1[e], __int_as_float(cols1[e]));
    }
    if (e < NNZ2) {
        int r = rows2[e];
        int p = atomicAdd(&g_cnt2[r], 1);
        if (p < STRIDE) e2[r * STRIDE + p] = make_float2(w2[e], __int_as_float(cols2[e]));
    }
}

// Counting sort of rows by edge count -> desc[slot] = (row<<8)|cnt.
// Equal counts land adjacent, so warps (32 consecutive slots) have uniform
// trip counts. block 0: layer 1, block 1: layer 2.
__global__ void k_sort() {
    const int N     = (blockIdx.x == 0) ? D_HID : D_OUT;
    int*      cnt   = (blockIdx.x == 0) ? g_cnt1 : g_cnt2;
    int*      desc  = (blockIdx.x == 0) ? g_desc1 : g_desc2;
    __shared__ int hist[STRIDE + 1];
    __shared__ int cur[STRIDE + 1];
    const int t = threadIdx.x;
    for (int i = t; i <= STRIDE; i += 256) hist[i] = 0;
    __syncthreads();
    for (int r = t; r < N; r += 256) {
        int c = min(cnt[r], STRIDE);
        atomicAdd(&hist[c], 1);
    }
    __syncthreads();
    if (t == 0) {
        int s = 0;
        for (int i = 0; i <= STRIDE; i++) { cur[i] = s; s += hist[i]; }
    }
    __syncthreads();
    for (int r = t; r < N; r += 256) {
        int c = min(cnt[r], STRIDE);
        int p = atomicAdd(&cur[c], 1);
        desc[p] = (r << 8) | c;
    }
}

// ---------------- fused sparse MLP -------------------------------------------
// Tiles fp16, transposed: col c occupies 32B (16 halves) = two 16B chunks.
// Chunk h (h=0: batches 0..7, h=1: 8..15) lives at uint4 index c*2 + (h ^ bit),
// bit=(c>>2)&1 — spreads LDS.128 start banks over all 8 classes for random c.
__device__ __forceinline__ float sigmoidf_fast(float v) {
    return __fdividef(1.0f, 1.0f + __expf(-v));
}

__device__ __forceinline__ void proc16(const uint4* __restrict__ t4, float w, int c,
                                       float a[16]) {
    int   bit = (c >> 2) & 1;
    uint4 q0  = t4[c * 2 + bit];         // batches 0..7
    uint4 q1  = t4[c * 2 + (bit ^ 1)];   // batches 8..15
    float2 f;
    f = __half22float2(*reinterpret_cast<__half2*>(&q0.x)); a[0] += w*f.x; a[1] += w*f.y;
    f = __half22float2(*reinterpret_cast<__half2*>(&q0.y)); a[2] += w*f.x; a[3] += w*f.y;
    f = __half22float2(*reinterpret_cast<__half2*>(&q0.z)); a[4] += w*f.x; a[5] += w*f.y;
    f = __half22float2(*reinterpret_cast<__half2*>(&q0.w)); a[6] += w*f.x; a[7] += w*f.y;
    f = __half22float2(*reinterpret_cast<__half2*>(&q1.x)); a[8] += w*f.x; a[9] += w*f.y;
    f = __half22float2(*reinterpret_cast<__half2*>(&q1.y)); a[10]+= w*f.x; a[11]+= w*f.y;
    f = __half22float2(*reinterpret_cast<__half2*>(&q1.z)); a[12]+= w*f.x; a[13]+= w*f.y;
    f = __half22float2(*reinterpret_cast<__half2*>(&q1.w)); a[14]+= w*f.x; a[15]+= w*f.y;
}

__device__ __forceinline__ void proc8(const uint4* __restrict__ t4, float w, int c,
                                      int half, float a[8]) {
    int   bit = (c >> 2) & 1;
    uint4 q   = t4[c * 2 + (half ^ bit)];
    float2 f;
    f = __half22float2(*reinterpret_cast<__half2*>(&q.x)); a[0] += w*f.x; a[1] += w*f.y;
    f = __half22float2(*reinterpret_cast<__half2*>(&q.y)); a[2] += w*f.x; a[3] += w*f.y;
    f = __half22float2(*reinterpret_cast<__half2*>(&q.z)); a[4] += w*f.x; a[5] += w*f.y;
    f = __half22float2(*reinterpret_cast<__half2*>(&q.w)); a[6] += w*f.x; a[7] += w*f.y;
}

__device__ __forceinline__ void do_row1(const uint4* __restrict__ xs4,
                                        __half* __restrict__ hs,
                                        const float* __restrict__ b1, int d) {
    const int     r  = d >> 8;
    const int     n  = d & 255;
    const float4* ep = g_edge1 + r * (STRIDE / 2);
    const float   bias = __ldg(b1 + r);
    float a[16];
    #pragma unroll
    for (int k = 0; k < 16; k++) a[k] = bias;
    const int npair = n >> 1;
    #pragma unroll 2
    for (int i = 0; i < npair; i++) {
        float4 e = ep[i];
        proc16(xs4, e.x, __float_as_int(e.y), a);
        proc16(xs4, e.z, __float_as_int(e.w), a);
    }
    if (n & 1) {
        float2 el = reinterpret_cast<const float2*>(ep)[n - 1];
        proc16(xs4, el.x, __float_as_int(el.y), a);
    }
    __half2 h2v[8];
    #pragma unroll
    for (int k = 0; k < 8; k++)
        h2v[k] = __floats2half2_rn(sigmoidf_fast(a[2 * k]), sigmoidf_fast(a[2 * k + 1]));
    const int bit = (r >> 2) & 1;
    uint4* h4 = reinterpret_cast<uint4*>(hs);
    h4[r * 2 + bit]       = *reinterpret_cast<uint4*>(&h2v[0]);
    h4[r * 2 + (bit ^ 1)] = *reinterpret_cast<uint4*>(&h2v[4]);
}

__global__ __launch_bounds__(1024, 1)
void k_fused(const float* __restrict__ x, const float* __restrict__ b1,
             const float* __restrict__ b2, float* __restrict__ out) {
    extern __shared__ __half smem_h[];
    __half* xs = smem_h;                 // [D_IN][16] fp16 swizzled  = 128 KB
    __half* hs = smem_h + D_IN * TB;     // [D_HID][16] fp16 swizzled =  64 KB

    const int tid = threadIdx.x;
    const int b0  = blockIdx.x * TB;

    // ---- load x tile: fp32 -> fp16, transposed + chunk-swizzled ----
    {
        const int p    = tid & 7;        // batch pair (batches 2p, 2p+1)
        const int slot = tid >> 3;       // 0..127
        const float4* rA = reinterpret_cast<const float4*>(x + (size_t)(b0 + 2 * p) * D_IN);
        const float4* rB = reinterpret_cast<const float4*>(x + (size_t)(b0 + 2 * p + 1) * D_IN);
        __half2* x2 = reinterpret_cast<__half2*>(xs);
        #pragma unroll
        for (int it = 0; it < 8; it++) {
            int    c4 = it * 128 + slot;         // float4-column 0..1023
            float4 va = __ldg(rA + c4);
            float4 vb = __ldg(rB + c4);
            int    pp = p ^ ((c4 & 1) << 2);     // bit=(c>>2)&1 == c4&1 for j<4
            int    wb = c4 * 32 + pp;            // half2-word base
            x2[wb + 0]  = __floats2half2_rn(va.x, vb.x);
            x2[wb + 8]  = __floats2half2_rn(va.y, vb.y);
            x2[wb + 16] = __floats2half2_rn(va.z, vb.z);
            x2[wb + 24] = __floats2half2_rn(va.w, vb.w);
        }
    }
    __syncthreads();

    // ---- layer 1: two count-matched rows per thread ----
    {
        const uint4* xs4 = reinterpret_cast<const uint4*>(xs);
        const int d0 = g_desc1[tid];
        const int d1 = g_desc1[D_HID - 1 - tid];   // pair big with small
        do_row1(xs4, hs, b1, d0);
        do_row1(xs4, hs, b1, d1);
    }
    __syncthreads();

    // ---- layer 2: thread = (sorted row, batch half) ----
    {
        const uint4* hs4  = reinterpret_cast<const uint4*>(hs);
        const int    slot = tid & 511;
        const int    half = tid >> 9;
        const int    d    = g_desc2[slot];
        const int    r    = d >> 8;
        const int    n    = d & 255;
        const float4* ep  = g_edge2 + r * (STRIDE / 2);
        const float  bias = __ldg(b2 + r);
        float a[8];
        #pragma unroll
        for (int k = 0; k < 8; k++) a[k] = bias;
        const int npair = n >> 1;
        #pragma unroll 2
        for (int i = 0; i < npair; i++) {
            float4 e = ep[i];
            proc8(hs4, e.x, __float_as_int(e.y), half, a);
            proc8(hs4, e.z, __float_as_int(e.w), half, a);
        }
        if (n & 1) {
            float2 el = reinterpret_cast<const float2*>(ep)[n - 1];
            proc8(hs4, el.x, __float_as_int(el.y), half, a);
        }
        // stage to padded smem (overlays xs; layer 2 only reads hs)
        float* os = reinterpret_cast<float*>(smem_h);   // [512][17] f32 = 34 KB
        int    ob = r * 17 + half * 8;
        #pragma unroll
        for (int k = 0; k < 8; k++) os[ob + k] = a[k];
    }
    __syncthreads();

    // ---- coalesced output copy ----
    {
        const float* os = reinterpret_cast<const float*>(smem_h);
        #pragma unroll
        for (int k = 0; k < 8; k++) {
            int idx = k * 1024 + tid;
            int b   = idx >> 9;      // 0..15
            int o   = idx & 511;
            out[(size_t)(b0 + b) * D_OUT + o] = os[o * 17 + b];
        }
    }
}

// ---------------- launch: 4-kernel period, k_fused at index 3 ----------------
extern "C" void kernel_launch(void* const* d_in, const int* in_sizes, int n_in,
                              void* d_out, int out_size) {
    const float* x     = (const float*)d_in[0];
    const float* w1    = (const float*)d_in[1];
    const float* b1    = (const float*)d_in[2];
    const float* w2    = (const float*)d_in[3];
    const float* b2    = (const float*)d_in[4];
    const int*   rows1 = (const int*)d_in[5];
    const int*   cols1 = (const int*)d_in[6];
    const int*   rows2 = (const int*)d_in[7];
    const int*   cols2 = (const int*)d_in[8];
    float*       out   = (float*)d_out;

    k_zero<<<8, 256>>>();
    k_scatter<<<NNZ1 / 256, 256>>>(w1, rows1, cols1, w2, rows2, cols2);
    k_sort<<<2, 256>>>();

    const size_t SMEM = (size_t)(D_IN + D_HID) * TB * sizeof(__half); // 192 KB
    cudaFuncSetAttribute(k_fused, cudaFuncAttributeMaxDynamicSharedMemorySize, (int)SMEM);
    k_fused<<<NBATCH / TB, 1024, SMEM>>>(x, b1, b2, out);
}